// round 1
// baseline (speedup 1.0000x reference)
#include <cuda_runtime.h>
#include <cstdint>

// Problem constants
constexpr int E_ = 8;
constexpr int D_ = 1024;
constexpr int H_ = 2816;
constexpr int T_ = 16384;

// Tiling
constexpr int BM = 128;
constexpr int BN = 64;
constexpr int BK = 16;
constexpr int PADW = BK + 4;   // 20 floats/row -> conflict-free fragment LDS

// Scratch for intermediate h = silu(x@w1^T) * (x@w3^T), fp32 [T, H]
__device__ float g_h[(size_t)T_ * H_];

__device__ __forceinline__ uint32_t f2tf32(float x) {
    uint32_t r;
    asm("cvt.rna.tf32.f32 %0, %1;" : "=r"(r) : "f"(x));
    return r;
}

__device__ __forceinline__ void mma_tf32(float c[4], const uint32_t a[4], const uint32_t b[2]) {
    asm volatile(
        "mma.sync.aligned.m16n8k8.row.col.f32.tf32.tf32.f32 "
        "{%0,%1,%2,%3}, {%4,%5,%6,%7}, {%8,%9}, {%0,%1,%2,%3};\n"
        : "+f"(c[0]), "+f"(c[1]), "+f"(c[2]), "+f"(c[3])
        : "r"(a[0]), "r"(a[1]), "r"(a[2]), "r"(a[3]),
          "r"(b[0]), "r"(b[1]));
}

// Compute expert offset/count from the 8 device-resident counts.
__device__ __forceinline__ void expert_seg(const int* __restrict__ cnts, int e,
                                           int& off, int& cnt) {
    off = 0; cnt = 0;
    #pragma unroll
    for (int i = 0; i < E_; i++) {
        int c = __ldg(&cnts[i]);
        if (i < e) off += c;
        if (i == e) cnt = c;
    }
}

// ---------------------------------------------------------------------------
// Kernel 1: h = silu(x @ w1[e]^T) * (x @ w3[e]^T)  -> g_h  (fp32)
// Grid: (H/BN, T/BM, E). Block: 256 threads (8 warps as 4 x 2).
// ---------------------------------------------------------------------------
__global__ void __launch_bounds__(256, 2)
moe_up_kernel(const float* __restrict__ x,
              const float* __restrict__ w1,
              const float* __restrict__ w3,
              const int* __restrict__ cnts)
{
    const int e = blockIdx.z;
    int off, cnt;
    expert_seg(cnts, e, off, cnt);

    const int mt = blockIdx.y;
    if (mt * BM >= cnt) return;
    const int row0 = off + mt * BM;
    const int rows_valid = min(BM, cnt - mt * BM);
    const int n0 = blockIdx.x * BN;

    __shared__ uint32_t As[BM][PADW];
    __shared__ uint32_t B1s[BN][PADW];
    __shared__ uint32_t B3s[BN][PADW];

    const float* w1e = w1 + (size_t)e * H_ * D_;
    const float* w3e = w3 + (size_t)e * H_ * D_;

    const int tid  = threadIdx.x;
    const int lane = tid & 31;
    const int wid  = tid >> 5;
    const int wm   = wid & 3;    // warp row (0..3) -> 32 rows each
    const int wn   = wid >> 2;   // warp col (0..1) -> 32 cols each
    const int g    = lane >> 2;  // group id (0..7)
    const int tg   = lane & 3;   // thread in group (0..3)

    float acc1[2][4][4] = {};
    float acc3[2][4][4] = {};

    const int lr = tid >> 2;        // 0..63
    const int lc = (tid & 3) * 4;   // 0,4,8,12

    for (int kt = 0; kt < D_; kt += BK) {
        // ---- stage A (x tile, 128 x 16) ----
        #pragma unroll
        for (int h = 0; h < 2; h++) {
            int r = lr + h * 64;
            int grow = row0 + r;
            float4 v = make_float4(0.f, 0.f, 0.f, 0.f);
            if (grow < T_)
                v = *reinterpret_cast<const float4*>(x + (size_t)grow * D_ + kt + lc);
            As[r][lc + 0] = f2tf32(v.x);
            As[r][lc + 1] = f2tf32(v.y);
            As[r][lc + 2] = f2tf32(v.z);
            As[r][lc + 3] = f2tf32(v.w);
        }
        // ---- stage B1/B3 (w tiles, 64 x 16 each) ----
        {
            size_t boff = (size_t)(n0 + lr) * D_ + kt + lc;
            float4 v1 = *reinterpret_cast<const float4*>(w1e + boff);
            float4 v3 = *reinterpret_cast<const float4*>(w3e + boff);
            B1s[lr][lc + 0] = f2tf32(v1.x);
            B1s[lr][lc + 1] = f2tf32(v1.y);
            B1s[lr][lc + 2] = f2tf32(v1.z);
            B1s[lr][lc + 3] = f2tf32(v1.w);
            B3s[lr][lc + 0] = f2tf32(v3.x);
            B3s[lr][lc + 1] = f2tf32(v3.y);
            B3s[lr][lc + 2] = f2tf32(v3.z);
            B3s[lr][lc + 3] = f2tf32(v3.w);
        }
        __syncthreads();

        #pragma unroll
        for (int kk = 0; kk < BK; kk += 8) {
            uint32_t a[2][4];
            #pragma unroll
            for (int mi = 0; mi < 2; mi++) {
                int rb = wm * 32 + mi * 16;
                a[mi][0] = As[rb + g][kk + tg];
                a[mi][1] = As[rb + g + 8][kk + tg];
                a[mi][2] = As[rb + g][kk + tg + 4];
                a[mi][3] = As[rb + g + 8][kk + tg + 4];
            }
            #pragma unroll
            for (int ni = 0; ni < 4; ni++) {
                int nb = wn * 32 + ni * 8;
                uint32_t b1[2] = { B1s[nb + g][kk + tg], B1s[nb + g][kk + tg + 4] };
                uint32_t b3[2] = { B3s[nb + g][kk + tg], B3s[nb + g][kk + tg + 4] };
                #pragma unroll
                for (int mi = 0; mi < 2; mi++) {
                    mma_tf32(acc1[mi][ni], a[mi], b1);
                    mma_tf32(acc3[mi][ni], a[mi], b3);
                }
            }
        }
        __syncthreads();
    }

    // ---- epilogue: SwiGLU, masked store to g_h ----
    #pragma unroll
    for (int mi = 0; mi < 2; mi++) {
        #pragma unroll
        for (int ni = 0; ni < 4; ni++) {
            #pragma unroll
            for (int v = 0; v < 4; v++) {
                int row = wm * 32 + mi * 16 + g + ((v >> 1) ? 8 : 0);
                int col = wn * 32 + ni * 8 + tg * 2 + (v & 1);
                if (row < rows_valid) {
                    float h1 = acc1[mi][ni][v];
                    float h3 = acc3[mi][ni][v];
                    float s = h1 / (1.0f + __expf(-h1));
                    g_h[(size_t)(row0 + row) * H_ + (n0 + col)] = s * h3;
                }
            }
        }
    }
}

// ---------------------------------------------------------------------------
// Kernel 2: out = h @ w2[e]^T   (K = H = 2816, N = D = 1024)
// Grid: (D/BN, T/BM, E). Block: 256 threads.
// ---------------------------------------------------------------------------
__global__ void __launch_bounds__(256, 2)
moe_down_kernel(const float* __restrict__ w2,
                const int* __restrict__ cnts,
                float* __restrict__ out)
{
    const int e = blockIdx.z;
    int off, cnt;
    expert_seg(cnts, e, off, cnt);

    const int mt = blockIdx.y;
    if (mt * BM >= cnt) return;
    const int row0 = off + mt * BM;
    const int rows_valid = min(BM, cnt - mt * BM);
    const int n0 = blockIdx.x * BN;

    __shared__ uint32_t As[BM][PADW];
    __shared__ uint32_t Bs[BN][PADW];

    const float* w2e = w2 + (size_t)e * D_ * H_;

    const int tid  = threadIdx.x;
    const int lane = tid & 31;
    const int wid  = tid >> 5;
    const int wm   = wid & 3;
    const int wn   = wid >> 2;
    const int g    = lane >> 2;
    const int tg   = lane & 3;

    float acc[2][4][4] = {};

    const int lr = tid >> 2;
    const int lc = (tid & 3) * 4;

    for (int kt = 0; kt < H_; kt += BK) {
        #pragma unroll
        for (int h = 0; h < 2; h++) {
            int r = lr + h * 64;
            int grow = row0 + r;
            float4 v = make_float4(0.f, 0.f, 0.f, 0.f);
            if (grow < T_)
                v = *reinterpret_cast<const float4*>(g_h + (size_t)grow * H_ + kt + lc);
            As[r][lc + 0] = f2tf32(v.x);
            As[r][lc + 1] = f2tf32(v.y);
            As[r][lc + 2] = f2tf32(v.z);
            As[r][lc + 3] = f2tf32(v.w);
        }
        {
            size_t boff = (size_t)(n0 + lr) * H_ + kt + lc;
            float4 v = *reinterpret_cast<const float4*>(w2e + boff);
            Bs[lr][lc + 0] = f2tf32(v.x);
            Bs[lr][lc + 1] = f2tf32(v.y);
            Bs[lr][lc + 2] = f2tf32(v.z);
            Bs[lr][lc + 3] = f2tf32(v.w);
        }
        __syncthreads();

        #pragma unroll
        for (int kk = 0; kk < BK; kk += 8) {
            uint32_t a[2][4];
            #pragma unroll
            for (int mi = 0; mi < 2; mi++) {
                int rb = wm * 32 + mi * 16;
                a[mi][0] = As[rb + g][kk + tg];
                a[mi][1] = As[rb + g + 8][kk + tg];
                a[mi][2] = As[rb + g][kk + tg + 4];
                a[mi][3] = As[rb + g + 8][kk + tg + 4];
            }
            #pragma unroll
            for (int ni = 0; ni < 4; ni++) {
                int nb = wn * 32 + ni * 8;
                uint32_t b[2] = { Bs[nb + g][kk + tg], Bs[nb + g][kk + tg + 4] };
                #pragma unroll
                for (int mi = 0; mi < 2; mi++) {
                    mma_tf32(acc[mi][ni], a[mi], b);
                }
            }
        }
        __syncthreads();
    }

    #pragma unroll
    for (int mi = 0; mi < 2; mi++) {
        #pragma unroll
        for (int ni = 0; ni < 4; ni++) {
            #pragma unroll
            for (int v = 0; v < 4; v++) {
                int row = wm * 32 + mi * 16 + g + ((v >> 1) ? 8 : 0);
                int col = wn * 32 + ni * 8 + tg * 2 + (v & 1);
                if (row < rows_valid) {
                    out[(size_t)(row0 + row) * D_ + (n0 + col)] = acc[mi][ni][v];
                }
            }
        }
    }
}

// ---------------------------------------------------------------------------
// Launch
// Inputs (metadata order): x [T*D] f32, w1 [E*H*D] f32, w2 [E*D*H] f32,
//                          w3 [E*H*D] f32, num_tokens_per_expert [E] i32.
// Output: [T*D] f32.
// ---------------------------------------------------------------------------
extern "C" void kernel_launch(void* const* d_in, const int* in_sizes, int n_in,
                              void* d_out, int out_size) {
    const float* x    = (const float*)d_in[0];
    const float* w1   = (const float*)d_in[1];
    const float* w2   = (const float*)d_in[2];
    const float* w3   = (const float*)d_in[3];
    const int*   cnts = (const int*)d_in[4];
    float* out = (float*)d_out;

    // Padding rows (beyond sum(counts)) must be zero; d_out is poisoned.
    cudaMemsetAsync(d_out, 0, (size_t)out_size * sizeof(float));

    dim3 block(256);
    dim3 g1(H_ / BN, T_ / BM, E_);
    moe_up_kernel<<<g1, block>>>(x, w1, w3, cnts);

    dim3 g2(D_ / BN, T_ / BM, E_);
    moe_down_kernel<<<g2, block>>>(w2, cnts, out);
}

// round 4
// speedup vs baseline: 1.6695x; 1.6695x over previous
#include <cuda_runtime.h>
#include <cstdint>

// ---------------------------------------------------------------------------
// Problem constants
// ---------------------------------------------------------------------------
constexpr int E_ = 8;
constexpr int D_ = 1024;
constexpr int H_ = 2816;
constexpr int T_ = 16384;

// CTA tile 128x128, K-chunk 32 (128B rows -> SW128 swizzle)
constexpr int BM = 128;
constexpr int BN = 128;
constexpr int BK = 32;
constexpr int NKT_UP = D_ / BK;   // 32
constexpr int NKT_DN = H_ / BK;   // 88

constexpr int TILE_A = BM * BK * 4;          // 16384 B
constexpr int TILE_B = BN * BK * 4;          // 16384 B
constexpr int STG_UP = TILE_A + 2 * TILE_B;  // 49152 (A, B1, B3)
constexpr int STG_DN = TILE_A + TILE_B;      // 32768 (A, B)
constexpr int SMEM_UP = 2 * STG_UP;          // 98304
constexpr int SMEM_DN = 2 * STG_DN;          // 65536

// Intermediate h = silu(x@w1^T)*(x@w3^T), fp32 [T, H]
__device__ float g_h[(size_t)T_ * H_];

// ---------------------------------------------------------------------------
// Helpers
// ---------------------------------------------------------------------------
__device__ __forceinline__ uint32_t smem_to_u32(const void* p) {
    uint32_t a;
    asm("{ .reg .u64 t; cvta.to.shared.u64 t, %1; cvt.u32.u64 %0, t; }"
        : "=r"(a) : "l"(p));
    return a;
}

__device__ __forceinline__ uint32_t f2tf32(float x) {
    uint32_t r;
    asm("cvt.rna.tf32.f32 %0, %1;" : "=r"(r) : "f"(x));
    return r;
}
__device__ __forceinline__ uint32_t cvt_frag(uint32_t v) {
    return f2tf32(__uint_as_float(v));
}

// swizzled byte offset inside a [rows][32 f32] tile with 128B rows
__device__ __forceinline__ uint32_t sw_off(int row, int colb) {
    return (uint32_t)(row * 128) + ((uint32_t)colb ^ (((uint32_t)row & 7u) << 4));
}

__device__ __forceinline__ void cp16(uint32_t saddr, const void* gaddr, int sz) {
    asm volatile("cp.async.cg.shared.global [%0], [%1], 16, %2;"
                 :: "r"(saddr), "l"(gaddr), "r"(sz) : "memory");
}
#define CP_COMMIT() asm volatile("cp.async.commit_group;" ::: "memory")
#define CP_WAIT1()  asm volatile("cp.async.wait_group 1;" ::: "memory")
#define CP_WAIT0()  asm volatile("cp.async.wait_group 0;" ::: "memory")

__device__ __forceinline__ void ldsm4(uint32_t r[4], uint32_t addr) {
    asm volatile("ldmatrix.sync.aligned.m8n8.x4.shared.b16 {%0,%1,%2,%3}, [%4];"
                 : "=r"(r[0]), "=r"(r[1]), "=r"(r[2]), "=r"(r[3]) : "r"(addr));
}

__device__ __forceinline__ void mma8(float c[4], const uint32_t a[4], const uint32_t b[2]) {
    asm volatile(
        "mma.sync.aligned.m16n8k8.row.col.f32.tf32.tf32.f32 "
        "{%0,%1,%2,%3}, {%4,%5,%6,%7}, {%8,%9}, {%0,%1,%2,%3};\n"
        : "+f"(c[0]), "+f"(c[1]), "+f"(c[2]), "+f"(c[3])
        : "r"(a[0]), "r"(a[1]), "r"(a[2]), "r"(a[3]), "r"(b[0]), "r"(b[1]));
}

__device__ __forceinline__ void expert_seg(const int* __restrict__ cnts, int e,
                                           int& off, int& cnt) {
    off = 0; cnt = 0;
    #pragma unroll
    for (int i = 0; i < E_; i++) {
        int c = __ldg(&cnts[i]);
        if (i < e) off += c;
        if (i == e) cnt = c;
    }
}

// Stage a ROWS x 32 f32 tile via cp.async (raw f32, swizzled dst).
template <int ROWS>
__device__ __forceinline__ void stage_cp(uint32_t sbuf, const float* __restrict__ src,
                                         int grow0, int ld, int kt, int tid, int rowlim) {
    #pragma unroll
    for (int i = 0; i < ROWS * 8 / 256; i++) {
        int idx = tid + i * 256;
        int r = idx >> 3, c4 = idx & 7;
        int grow = grow0 + r;
        bool ok = grow < rowlim;
        const float* g = ok ? (src + (size_t)grow * ld + kt * BK + c4 * 4) : src;
        cp16(sbuf + sw_off(r, c4 * 16), g, ok ? 16 : 0);
    }
}

// ---------------------------------------------------------------------------
// Kernel 1 (up): g_h = silu(x@w1^T) * (x@w3^T)
// Grid: (H/128=22, T/128, E). Block: 256 threads (8 warps, 2x4).
// ---------------------------------------------------------------------------
__global__ void __launch_bounds__(256, 1)
moe_up(const float* __restrict__ x,
       const float* __restrict__ w1,
       const float* __restrict__ w3,
       const int* __restrict__ cnts) {
    const int e = blockIdx.z;
    int off, cnt;
    expert_seg(cnts, e, off, cnt);
    if ((int)blockIdx.y * BM >= cnt) return;
    const int row0 = off + blockIdx.y * BM;
    const int rows_valid = min(BM, cnt - blockIdx.y * BM);
    const int n0 = blockIdx.x * BN;

    extern __shared__ char smem[];
    const uint32_t sb = smem_to_u32(smem);
    const int tid = threadIdx.x, wid = tid >> 5, lane = tid & 31;
    const int wm = wid & 1, wn = wid >> 1;          // 2 x 4 warp grid, warp tile 64x32
    const int lrow = lane & 7, grp = lane >> 3;

    const float* w1e = w1 + (size_t)e * H_ * D_;
    const float* w3e = w3 + (size_t)e * H_ * D_;

    // ldsm address components
    const uint32_t xm = (uint32_t)lrow << 4;
    uint32_t rowA[4], rowB[2];
    #pragma unroll
    for (int mi = 0; mi < 4; mi++)
        rowA[mi] = (uint32_t)((wm * 64 + mi * 16 + (grp & 1) * 8 + lrow) * 128);
    #pragma unroll
    for (int pr = 0; pr < 2; pr++)
        rowB[pr] = (uint32_t)((wn * 32 + pr * 16 + (grp >> 1) * 8 + lrow) * 128);
    const uint32_t cselA = (uint32_t)((grp >> 1) * 16);
    const uint32_t cselB = (uint32_t)((grp & 1) * 16);

    float acc1[4][4][4] = {};
    float acc3[4][4][4] = {};

    // stage tile 0
    {
        uint32_t b = sb;
        stage_cp<BM>(b, x, row0, D_, 0, tid, T_);
        stage_cp<BN>(b + TILE_A, w1e, n0, D_, 0, tid, 0x40000000);
        stage_cp<BN>(b + TILE_A + TILE_B, w3e, n0, D_, 0, tid, 0x40000000);
        CP_COMMIT();
    }

    for (int kt = 0; kt < NKT_UP; kt++) {
        const int s = kt & 1;
        if (kt + 1 < NKT_UP) {
            uint32_t b = sb + (s ^ 1) * STG_UP;
            stage_cp<BM>(b, x, row0, D_, kt + 1, tid, T_);
            stage_cp<BN>(b + TILE_A, w1e, n0, D_, kt + 1, tid, 0x40000000);
            stage_cp<BN>(b + TILE_A + TILE_B, w3e, n0, D_, kt + 1, tid, 0x40000000);
            CP_COMMIT();
            CP_WAIT1();
        } else {
            CP_WAIT0();
        }
        __syncthreads();

        const uint32_t bA = sb + s * STG_UP;
        const uint32_t bB1 = bA + TILE_A;
        const uint32_t bB3 = bB1 + TILE_B;
        #pragma unroll
        for (int kki = 0; kki < 4; kki++) {
            const uint32_t ca = ((uint32_t)(kki * 32) + cselA) ^ xm;
            const uint32_t cb = ((uint32_t)(kki * 32) + cselB) ^ xm;
            uint32_t a[4][4], b1f[4][2], b3f[4][2], t[4];
            #pragma unroll
            for (int mi = 0; mi < 4; mi++) ldsm4(a[mi], bA + rowA[mi] + ca);
            #pragma unroll
            for (int pr = 0; pr < 2; pr++) {
                ldsm4(t, bB1 + rowB[pr] + cb);
                b1f[2*pr][0] = t[0]; b1f[2*pr][1] = t[1];
                b1f[2*pr+1][0] = t[2]; b1f[2*pr+1][1] = t[3];
                ldsm4(t, bB3 + rowB[pr] + cb);
                b3f[2*pr][0] = t[0]; b3f[2*pr][1] = t[1];
                b3f[2*pr+1][0] = t[2]; b3f[2*pr+1][1] = t[3];
            }
            #pragma unroll
            for (int mi = 0; mi < 4; mi++)
                #pragma unroll
                for (int j = 0; j < 4; j++) a[mi][j] = cvt_frag(a[mi][j]);
            #pragma unroll
            for (int ni = 0; ni < 4; ni++)
                #pragma unroll
                for (int j = 0; j < 2; j++) {
                    b1f[ni][j] = cvt_frag(b1f[ni][j]);
                    b3f[ni][j] = cvt_frag(b3f[ni][j]);
                }
            #pragma unroll
            for (int mi = 0; mi < 4; mi++)
                #pragma unroll
                for (int ni = 0; ni < 4; ni++) {
                    mma8(acc1[mi][ni], a[mi], b1f[ni]);
                    mma8(acc3[mi][ni], a[mi], b3f[ni]);
                }
        }
        __syncthreads();
    }

    // epilogue: SwiGLU, masked float2 stores
    const int g = lane >> 2, tg = lane & 3;
    #pragma unroll
    for (int mi = 0; mi < 4; mi++) {
        const int r0 = wm * 64 + mi * 16 + g;
        #pragma unroll
        for (int ni = 0; ni < 4; ni++) {
            const int c = wn * 32 + ni * 8 + tg * 2;
            if (r0 < rows_valid) {
                float a0 = acc1[mi][ni][0], a1 = acc1[mi][ni][1];
                float g0 = acc3[mi][ni][0], g1 = acc3[mi][ni][1];
                float2 o;
                o.x = (a0 / (1.f + __expf(-a0))) * g0;
                o.y = (a1 / (1.f + __expf(-a1))) * g1;
                *reinterpret_cast<float2*>(g_h + (size_t)(row0 + r0) * H_ + n0 + c) = o;
            }
            if (r0 + 8 < rows_valid) {
                float a0 = acc1[mi][ni][2], a1 = acc1[mi][ni][3];
                float g0 = acc3[mi][ni][2], g1 = acc3[mi][ni][3];
                float2 o;
                o.x = (a0 / (1.f + __expf(-a0))) * g0;
                o.y = (a1 / (1.f + __expf(-a1))) * g1;
                *reinterpret_cast<float2*>(g_h + (size_t)(row0 + r0 + 8) * H_ + n0 + c) = o;
            }
        }
    }
}

// ---------------------------------------------------------------------------
// Kernel 2 (down): out = h @ w2^T. Grid: (D/128=8, T/128, E). 256 threads.
// ---------------------------------------------------------------------------
__global__ void __launch_bounds__(256, 1)
moe_down(const float* __restrict__ w2,
         const int* __restrict__ cnts,
         float* __restrict__ out) {
    const int e = blockIdx.z;
    int off, cnt;
    expert_seg(cnts, e, off, cnt);
    if ((int)blockIdx.y * BM >= cnt) return;
    const int row0 = off + blockIdx.y * BM;
    const int rows_valid = min(BM, cnt - blockIdx.y * BM);
    const int n0 = blockIdx.x * BN;

    extern __shared__ char smem[];
    const uint32_t sb = smem_to_u32(smem);
    const int tid = threadIdx.x, wid = tid >> 5, lane = tid & 31;
    const int wm = wid & 1, wn = wid >> 1;
    const int lrow = lane & 7, grp = lane >> 3;

    const float* w2e = w2 + (size_t)e * D_ * H_;

    const uint32_t xm = (uint32_t)lrow << 4;
    uint32_t rowA[4], rowB[2];
    #pragma unroll
    for (int mi = 0; mi < 4; mi++)
        rowA[mi] = (uint32_t)((wm * 64 + mi * 16 + (grp & 1) * 8 + lrow) * 128);
    #pragma unroll
    for (int pr = 0; pr < 2; pr++)
        rowB[pr] = (uint32_t)((wn * 32 + pr * 16 + (grp >> 1) * 8 + lrow) * 128);
    const uint32_t cselA = (uint32_t)((grp >> 1) * 16);
    const uint32_t cselB = (uint32_t)((grp & 1) * 16);

    float acc[4][4][4] = {};

    {
        uint32_t b = sb;
        stage_cp<BM>(b, g_h, row0, H_, 0, tid, T_);
        stage_cp<BN>(b + TILE_A, w2e, n0, H_, 0, tid, 0x40000000);
        CP_COMMIT();
    }

    for (int kt = 0; kt < NKT_DN; kt++) {
        const int s = kt & 1;
        if (kt + 1 < NKT_DN) {
            uint32_t b = sb + (s ^ 1) * STG_DN;
            stage_cp<BM>(b, g_h, row0, H_, kt + 1, tid, T_);
            stage_cp<BN>(b + TILE_A, w2e, n0, H_, kt + 1, tid, 0x40000000);
            CP_COMMIT();
            CP_WAIT1();
        } else {
            CP_WAIT0();
        }
        __syncthreads();

        const uint32_t bA = sb + s * STG_DN;
        const uint32_t bB = bA + TILE_A;
        #pragma unroll
        for (int kki = 0; kki < 4; kki++) {
            const uint32_t ca = ((uint32_t)(kki * 32) + cselA) ^ xm;
            const uint32_t cb = ((uint32_t)(kki * 32) + cselB) ^ xm;
            uint32_t a[4][4], bf[4][2], t[4];
            #pragma unroll
            for (int mi = 0; mi < 4; mi++) ldsm4(a[mi], bA + rowA[mi] + ca);
            #pragma unroll
            for (int pr = 0; pr < 2; pr++) {
                ldsm4(t, bB + rowB[pr] + cb);
                bf[2*pr][0] = t[0]; bf[2*pr][1] = t[1];
                bf[2*pr+1][0] = t[2]; bf[2*pr+1][1] = t[3];
            }
            #pragma unroll
            for (int mi = 0; mi < 4; mi++)
                #pragma unroll
                for (int j = 0; j < 4; j++) a[mi][j] = cvt_frag(a[mi][j]);
            #pragma unroll
            for (int ni = 0; ni < 4; ni++)
                #pragma unroll
                for (int j = 0; j < 2; j++) bf[ni][j] = cvt_frag(bf[ni][j]);
            #pragma unroll
            for (int mi = 0; mi < 4; mi++)
                #pragma unroll
                for (int ni = 0; ni < 4; ni++)
                    mma8(acc[mi][ni], a[mi], bf[ni]);
        }
        __syncthreads();
    }

    const int g = lane >> 2, tg = lane & 3;
    #pragma unroll
    for (int mi = 0; mi < 4; mi++) {
        const int r0 = wm * 64 + mi * 16 + g;
        #pragma unroll
        for (int ni = 0; ni < 4; ni++) {
            const int c = wn * 32 + ni * 8 + tg * 2;
            if (r0 < rows_valid) {
                float2 o = make_float2(acc[mi][ni][0], acc[mi][ni][1]);
                *reinterpret_cast<float2*>(out + (size_t)(row0 + r0) * D_ + n0 + c) = o;
            }
            if (r0 + 8 < rows_valid) {
                float2 o = make_float2(acc[mi][ni][2], acc[mi][ni][3]);
                *reinterpret_cast<float2*>(out + (size_t)(row0 + r0 + 8) * D_ + n0 + c) = o;
            }
        }
    }
}

// ---------------------------------------------------------------------------
// Launch. Inputs: x[T*D] f32, w1[E*H*D] f32, w2[E*D*H] f32, w3[E*H*D] f32,
//                 num_tokens_per_expert[E] i32. Output: [T*D] f32.
// ---------------------------------------------------------------------------
extern "C" void kernel_launch(void* const* d_in, const int* in_sizes, int n_in,
                              void* d_out, int out_size) {
    const float* x    = (const float*)d_in[0];
    const float* w1   = (const float*)d_in[1];
    const float* w2   = (const float*)d_in[2];
    const float* w3   = (const float*)d_in[3];
    const int*   cnts = (const int*)d_in[4];
    float* out = (float*)d_out;

    cudaFuncSetAttribute(moe_up,   cudaFuncAttributeMaxDynamicSharedMemorySize, SMEM_UP);
    cudaFuncSetAttribute(moe_down, cudaFuncAttributeMaxDynamicSharedMemorySize, SMEM_DN);

    // Padding rows (beyond sum(counts)) must be zero; d_out is poisoned.
    cudaMemsetAsync(d_out, 0, (size_t)out_size * sizeof(float));

    dim3 block(256);
    dim3 g1(H_ / BN, T_ / BM, E_);
    moe_up<<<g1, block, SMEM_UP>>>(x, w1, w3, cnts);

    dim3 g2(D_ / BN, T_ / BM, E_);
    moe_down<<<g2, block, SMEM_DN>>>(w2, cnts, out);
}

// round 6
// speedup vs baseline: 1.7821x; 1.0675x over previous
#include <cuda_runtime.h>
#include <cstdint>

// ---------------------------------------------------------------------------
// Problem constants
// ---------------------------------------------------------------------------
constexpr int E_ = 8;
constexpr int D_ = 1024;
constexpr int H_ = 2816;
constexpr int T_ = 16384;

// CTA tile 128x128, K-chunk 32 (128B rows -> SW128 swizzle), 3-stage pipeline
constexpr int BM = 128;
constexpr int BN = 128;
constexpr int BK = 32;
constexpr int NKT_UP = D_ / BK;   // 32
constexpr int NKT_DN = H_ / BK;   // 88
constexpr int NSTG = 3;

constexpr int TILE_A = BM * BK * 4;          // 16384 B
constexpr int TILE_B = BN * BK * 4;          // 16384 B
constexpr int STG_UP = TILE_A + 2 * TILE_B;  // 49152 (A, B1, B3)
constexpr int STG_DN = TILE_A + TILE_B;      // 32768 (A, B)
constexpr int SMEM_UP = NSTG * STG_UP;       // 147456
constexpr int SMEM_DN = NSTG * STG_DN;       // 98304

// tf32-bit scratch (rna-rounded once per launch)
__device__ uint32_t g_xt[(size_t)T_ * D_];
__device__ uint32_t g_w1t[(size_t)E_ * H_ * D_];
__device__ uint32_t g_w2t[(size_t)E_ * D_ * H_];
__device__ uint32_t g_w3t[(size_t)E_ * H_ * D_];
// Intermediate h = silu(x@w1^T)*(x@w3^T), stored as tf32 bits [T, H]
__device__ uint32_t g_h[(size_t)T_ * H_];

// ---------------------------------------------------------------------------
// Helpers
// ---------------------------------------------------------------------------
__device__ __forceinline__ uint32_t smem_to_u32(const void* p) {
    uint32_t a;
    asm("{ .reg .u64 t; cvta.to.shared.u64 t, %1; cvt.u32.u64 %0, t; }"
        : "=r"(a) : "l"(p));
    return a;
}

__device__ __forceinline__ uint32_t f2tf32(float x) {
    uint32_t r;
    asm("cvt.rna.tf32.f32 %0, %1;" : "=r"(r) : "f"(x));
    return r;
}

// swizzled byte offset inside a [rows][32 x u32] tile with 128B rows
__device__ __forceinline__ uint32_t sw_off(int row, int colb) {
    return (uint32_t)(row * 128) + ((uint32_t)colb ^ (((uint32_t)row & 7u) << 4));
}

__device__ __forceinline__ void cp16(uint32_t saddr, const void* gaddr, int sz) {
    asm volatile("cp.async.cg.shared.global [%0], [%1], 16, %2;"
                 :: "r"(saddr), "l"(gaddr), "r"(sz) : "memory");
}
#define CP_COMMIT() asm volatile("cp.async.commit_group;" ::: "memory")
#define CP_WAIT1()  asm volatile("cp.async.wait_group 1;" ::: "memory")
#define CP_WAIT0()  asm volatile("cp.async.wait_group 0;" ::: "memory")

__device__ __forceinline__ void ldsm4(uint32_t r[4], uint32_t addr) {
    asm volatile("ldmatrix.sync.aligned.m8n8.x4.shared.b16 {%0,%1,%2,%3}, [%4];"
                 : "=r"(r[0]), "=r"(r[1]), "=r"(r[2]), "=r"(r[3]) : "r"(addr));
}

__device__ __forceinline__ void mma8(float c[4], const uint32_t a[4], const uint32_t b[2]) {
    asm volatile(
        "mma.sync.aligned.m16n8k8.row.col.f32.tf32.tf32.f32 "
        "{%0,%1,%2,%3}, {%4,%5,%6,%7}, {%8,%9}, {%0,%1,%2,%3};\n"
        : "+f"(c[0]), "+f"(c[1]), "+f"(c[2]), "+f"(c[3])
        : "r"(a[0]), "r"(a[1]), "r"(a[2]), "r"(a[3]), "r"(b[0]), "r"(b[1]));
}

__device__ __forceinline__ void expert_seg(const int* __restrict__ cnts, int e,
                                           int& off, int& cnt) {
    off = 0; cnt = 0;
    #pragma unroll
    for (int i = 0; i < E_; i++) {
        int c = __ldg(&cnts[i]);
        if (i < e) off += c;
        if (i == e) cnt = c;
    }
}

// Stage a ROWS x 32 u32 tile via cp.async (raw bits, swizzled dst).
template <int ROWS>
__device__ __forceinline__ void stage_cp(uint32_t sbuf, const uint32_t* __restrict__ src,
                                         int grow0, int ld, int kt, int tid, int rowlim) {
    #pragma unroll
    for (int i = 0; i < ROWS * 8 / 256; i++) {
        int idx = tid + i * 256;
        int r = idx >> 3, c4 = idx & 7;
        int grow = grow0 + r;
        bool ok = grow < rowlim;
        const uint32_t* g = ok ? (src + (size_t)grow * ld + kt * BK + c4 * 4) : src;
        cp16(sbuf + sw_off(r, c4 * 16), g, ok ? 16 : 0);
    }
}

// ---------------------------------------------------------------------------
// Pre-convert: fp32 -> tf32 bits (rna), grid-stride float4
// ---------------------------------------------------------------------------
__global__ void __launch_bounds__(256)
preconv(const float* __restrict__ src, uint32_t* __restrict__ dst, size_t n4) {
    size_t i = (size_t)blockIdx.x * blockDim.x + threadIdx.x;
    size_t stride = (size_t)gridDim.x * blockDim.x;
    const float4* s = reinterpret_cast<const float4*>(src);
    uint4* d = reinterpret_cast<uint4*>(dst);
    for (; i < n4; i += stride) {
        float4 v = s[i];
        uint4 o;
        o.x = f2tf32(v.x); o.y = f2tf32(v.y);
        o.z = f2tf32(v.z); o.w = f2tf32(v.w);
        d[i] = o;
    }
}

// ---------------------------------------------------------------------------
// Kernel 1 (up): g_h = tf32(silu(x@w1^T) * (x@w3^T))
// Grid: (H/128=22, T/128, E). Block: 256 threads (8 warps, 2x4).
// ---------------------------------------------------------------------------
__global__ void __launch_bounds__(256, 1)
moe_up(const int* __restrict__ cnts) {
    const int e = blockIdx.z;
    int off, cnt;
    expert_seg(cnts, e, off, cnt);
    if ((int)blockIdx.y * BM >= cnt) return;
    const int row0 = off + blockIdx.y * BM;
    const int rows_valid = min(BM, cnt - blockIdx.y * BM);
    const int n0 = blockIdx.x * BN;

    extern __shared__ char smem[];
    const uint32_t sb = smem_to_u32(smem);
    const int tid = threadIdx.x, wid = tid >> 5, lane = tid & 31;
    const int wm = wid & 1, wn = wid >> 1;          // 2 x 4 warp grid, warp tile 64x32
    const int lrow = lane & 7, grp = lane >> 3;

    const uint32_t* w1e = g_w1t + (size_t)e * H_ * D_;
    const uint32_t* w3e = g_w3t + (size_t)e * H_ * D_;

    const uint32_t xm = (uint32_t)lrow << 4;
    uint32_t rowA[4], rowB[2];
    #pragma unroll
    for (int mi = 0; mi < 4; mi++)
        rowA[mi] = (uint32_t)((wm * 64 + mi * 16 + (grp & 1) * 8 + lrow) * 128);
    #pragma unroll
    for (int pr = 0; pr < 2; pr++)
        rowB[pr] = (uint32_t)((wn * 32 + pr * 16 + (grp >> 1) * 8 + lrow) * 128);
    const uint32_t cselA = (uint32_t)((grp >> 1) * 16);
    const uint32_t cselB = (uint32_t)((grp & 1) * 16);

    float acc1[4][4][4] = {};
    float acc3[4][4][4] = {};

    // preload stages 0 and 1
    #pragma unroll
    for (int p = 0; p < 2; p++) {
        uint32_t b = sb + p * STG_UP;
        stage_cp<BM>(b, g_xt, row0, D_, p, tid, T_);
        stage_cp<BN>(b + TILE_A, w1e, n0, D_, p, tid, 0x40000000);
        stage_cp<BN>(b + TILE_A + TILE_B, w3e, n0, D_, p, tid, 0x40000000);
        CP_COMMIT();
    }

    int s = 0, sp = 2;   // compute stage, prefetch stage
    for (int kt = 0; kt < NKT_UP; kt++) {
        if (kt + 1 < NKT_UP) CP_WAIT1(); else CP_WAIT0();
        __syncthreads();
        if (kt + 2 < NKT_UP) {
            uint32_t b = sb + sp * STG_UP;
            stage_cp<BM>(b, g_xt, row0, D_, kt + 2, tid, T_);
            stage_cp<BN>(b + TILE_A, w1e, n0, D_, kt + 2, tid, 0x40000000);
            stage_cp<BN>(b + TILE_A + TILE_B, w3e, n0, D_, kt + 2, tid, 0x40000000);
            CP_COMMIT();
        }
        const uint32_t bA = sb + s * STG_UP;
        const uint32_t bB1 = bA + TILE_A;
        const uint32_t bB3 = bB1 + TILE_B;
        #pragma unroll
        for (int kki = 0; kki < 4; kki++) {
            const uint32_t ca = ((uint32_t)(kki * 32) + cselA) ^ xm;
            const uint32_t cb = ((uint32_t)(kki * 32) + cselB) ^ xm;
            uint32_t a[4][4], b1f[4][2], b3f[4][2], t[4];
            #pragma unroll
            for (int mi = 0; mi < 4; mi++) ldsm4(a[mi], bA + rowA[mi] + ca);
            #pragma unroll
            for (int pr = 0; pr < 2; pr++) {
                ldsm4(t, bB1 + rowB[pr] + cb);
                b1f[2*pr][0] = t[0]; b1f[2*pr][1] = t[1];
                b1f[2*pr+1][0] = t[2]; b1f[2*pr+1][1] = t[3];
                ldsm4(t, bB3 + rowB[pr] + cb);
                b3f[2*pr][0] = t[0]; b3f[2*pr][1] = t[1];
                b3f[2*pr+1][0] = t[2]; b3f[2*pr+1][1] = t[3];
            }
            #pragma unroll
            for (int mi = 0; mi < 4; mi++)
                #pragma unroll
                for (int ni = 0; ni < 4; ni++) {
                    mma8(acc1[mi][ni], a[mi], b1f[ni]);
                    mma8(acc3[mi][ni], a[mi], b3f[ni]);
                }
        }
        s = s + 1 == NSTG ? 0 : s + 1;
        sp = sp + 1 == NSTG ? 0 : sp + 1;
        __syncthreads();
    }

    // epilogue: SwiGLU, rna-round to tf32 bits, masked stores
    const int g = lane >> 2, tg = lane & 3;
    #pragma unroll
    for (int mi = 0; mi < 4; mi++) {
        const int r0 = wm * 64 + mi * 16 + g;
        #pragma unroll
        for (int ni = 0; ni < 4; ni++) {
            const int c = wn * 32 + ni * 8 + tg * 2;
            if (r0 < rows_valid) {
                float a0 = acc1[mi][ni][0], a1 = acc1[mi][ni][1];
                float g0 = acc3[mi][ni][0], g1 = acc3[mi][ni][1];
                uint2 o;
                o.x = f2tf32((a0 / (1.f + __expf(-a0))) * g0);
                o.y = f2tf32((a1 / (1.f + __expf(-a1))) * g1);
                *reinterpret_cast<uint2*>(g_h + (size_t)(row0 + r0) * H_ + n0 + c) = o;
            }
            if (r0 + 8 < rows_valid) {
                float a0 = acc1[mi][ni][2], a1 = acc1[mi][ni][3];
                float g0 = acc3[mi][ni][2], g1 = acc3[mi][ni][3];
                uint2 o;
                o.x = f2tf32((a0 / (1.f + __expf(-a0))) * g0);
                o.y = f2tf32((a1 / (1.f + __expf(-a1))) * g1);
                *reinterpret_cast<uint2*>(g_h + (size_t)(row0 + r0 + 8) * H_ + n0 + c) = o;
            }
        }
    }
}

// ---------------------------------------------------------------------------
// Kernel 2 (down): out = h @ w2^T. Grid: (D/128=8, T/128, E). 256 threads.
// ---------------------------------------------------------------------------
__global__ void __launch_bounds__(256, 2)
moe_down(const int* __restrict__ cnts, float* __restrict__ out) {
    const int e = blockIdx.z;
    int off, cnt;
    expert_seg(cnts, e, off, cnt);
    if ((int)blockIdx.y * BM >= cnt) return;
    const int row0 = off + blockIdx.y * BM;
    const int rows_valid = min(BM, cnt - blockIdx.y * BM);
    const int n0 = blockIdx.x * BN;

    extern __shared__ char smem[];
    const uint32_t sb = smem_to_u32(smem);
    const int tid = threadIdx.x, wid = tid >> 5, lane = tid & 31;
    const int wm = wid & 1, wn = wid >> 1;
    const int lrow = lane & 7, grp = lane >> 3;

    const uint32_t* w2e = g_w2t + (size_t)e * D_ * H_;

    const uint32_t xm = (uint32_t)lrow << 4;
    uint32_t rowA[4], rowB[2];
    #pragma unroll
    for (int mi = 0; mi < 4; mi++)
        rowA[mi] = (uint32_t)((wm * 64 + mi * 16 + (grp & 1) * 8 + lrow) * 128);
    #pragma unroll
    for (int pr = 0; pr < 2; pr++)
        rowB[pr] = (uint32_t)((wn * 32 + pr * 16 + (grp >> 1) * 8 + lrow) * 128);
    const uint32_t cselA = (uint32_t)((grp >> 1) * 16);
    const uint32_t cselB = (uint32_t)((grp & 1) * 16);

    float acc[4][4][4] = {};

    #pragma unroll
    for (int p = 0; p < 2; p++) {
        uint32_t b = sb + p * STG_DN;
        stage_cp<BM>(b, g_h, row0, H_, p, tid, T_);
        stage_cp<BN>(b + TILE_A, w2e, n0, H_, p, tid, 0x40000000);
        CP_COMMIT();
    }

    int s = 0, sp = 2;
    for (int kt = 0; kt < NKT_DN; kt++) {
        if (kt + 1 < NKT_DN) CP_WAIT1(); else CP_WAIT0();
        __syncthreads();
        if (kt + 2 < NKT_DN) {
            uint32_t b = sb + sp * STG_DN;
            stage_cp<BM>(b, g_h, row0, H_, kt + 2, tid, T_);
            stage_cp<BN>(b + TILE_A, w2e, n0, H_, kt + 2, tid, 0x40000000);
            CP_COMMIT();
        }
        const uint32_t bA = sb + s * STG_DN;
        const uint32_t bB = bA + TILE_A;
        #pragma unroll
        for (int kki = 0; kki < 4; kki++) {
            const uint32_t ca = ((uint32_t)(kki * 32) + cselA) ^ xm;
            const uint32_t cb = ((uint32_t)(kki * 32) + cselB) ^ xm;
            uint32_t a[4][4], bf[4][2], t[4];
            #pragma unroll
            for (int mi = 0; mi < 4; mi++) ldsm4(a[mi], bA + rowA[mi] + ca);
            #pragma unroll
            for (int pr = 0; pr < 2; pr++) {
                ldsm4(t, bB + rowB[pr] + cb);
                bf[2*pr][0] = t[0]; bf[2*pr][1] = t[1];
                bf[2*pr+1][0] = t[2]; bf[2*pr+1][1] = t[3];
            }
            #pragma unroll
            for (int mi = 0; mi < 4; mi++)
                #pragma unroll
                for (int ni = 0; ni < 4; ni++)
                    mma8(acc[mi][ni], a[mi], bf[ni]);
        }
        s = s + 1 == NSTG ? 0 : s + 1;
        sp = sp + 1 == NSTG ? 0 : sp + 1;
        __syncthreads();
    }

    const int g = lane >> 2, tg = lane & 3;
    #pragma unroll
    for (int mi = 0; mi < 4; mi++) {
        const int r0 = wm * 64 + mi * 16 + g;
        #pragma unroll
        for (int ni = 0; ni < 4; ni++) {
            const int c = wn * 32 + ni * 8 + tg * 2;
            if (r0 < rows_valid) {
                float2 o = make_float2(acc[mi][ni][0], acc[mi][ni][1]);
                *reinterpret_cast<float2*>(out + (size_t)(row0 + r0) * D_ + n0 + c) = o;
            }
            if (r0 + 8 < rows_valid) {
                float2 o = make_float2(acc[mi][ni][2], acc[mi][ni][3]);
                *reinterpret_cast<float2*>(out + (size_t)(row0 + r0 + 8) * D_ + n0 + c) = o;
            }
        }
    }
}

// ---------------------------------------------------------------------------
// Launch. Inputs: x[T*D] f32, w1[E*H*D] f32, w2[E*D*H] f32, w3[E*H*D] f32,
//                 num_tokens_per_expert[E] i32. Output: [T*D] f32.
// ---------------------------------------------------------------------------
extern "C" void kernel_launch(void* const* d_in, const int* in_sizes, int n_in,
                              void* d_out, int out_size) {
    const float* x    = (const float*)d_in[0];
    const float* w1   = (const float*)d_in[1];
    const float* w2   = (const float*)d_in[2];
    const float* w3   = (const float*)d_in[3];
    const int*   cnts = (const int*)d_in[4];
    float* out = (float*)d_out;

    cudaFuncSetAttribute(moe_up,   cudaFuncAttributeMaxDynamicSharedMemorySize, SMEM_UP);
    cudaFuncSetAttribute(moe_down, cudaFuncAttributeMaxDynamicSharedMemorySize, SMEM_DN);

    uint32_t *xt, *w1t, *w2t, *w3t;
    cudaGetSymbolAddress((void**)&xt,  g_xt);
    cudaGetSymbolAddress((void**)&w1t, g_w1t);
    cudaGetSymbolAddress((void**)&w2t, g_w2t);
    cudaGetSymbolAddress((void**)&w3t, g_w3t);

    // Padding rows (beyond sum(counts)) must be zero; d_out is poisoned.
    cudaMemsetAsync(d_out, 0, (size_t)out_size * sizeof(float));

    // One-time (per launch) rna-rounding to tf32 bit patterns
    const size_t nx = (size_t)T_ * D_ / 4;
    const size_t nw = (size_t)E_ * H_ * D_ / 4;
    preconv<<<2048, 256>>>(x,  xt,  nx);
    preconv<<<4096, 256>>>(w1, w1t, nw);
    preconv<<<4096, 256>>>(w2, w2t, nw);
    preconv<<<4096, 256>>>(w3, w3t, nw);

    dim3 block(256);
    dim3 g1(H_ / BN, T_ / BM, E_);
    moe_up<<<g1, block, SMEM_UP>>>(cnts);

    dim3 g2(D_ / BN, T_ / BM, E_);
    moe_down<<<g2, block, SMEM_DN>>>(cnts, out);
}